// round 2
// baseline (speedup 1.0000x reference)
#include <cuda_runtime.h>
#include <cuda_bf16.h>

// WTA / row-wise top-k(=64) scatter-to-dense, exact incl. tie-breaking.
// Strategy: 1 CTA per row, row in registers (8x float4 per thread).
//   (a) order-preserving float->uint key map
//   (b) gather pass at fixed guess threshold map(1.5f) -> SMEM candidates
//       (warp-aggregated atomics); exact uint bisection over candidates
//       (full-row fallback keeps arbitrary inputs correct)
//   (c) tie check: if count(>=thr) > k, stable (lowest-column-first) rank
//       among ==thr elements, keep first k-count(>thr)  [rare path]
//   (d) streaming output pass from registers.

#define COLS 8192
#define TPB  256
#define VPT  (COLS / (TPB * 4))   // 8 float4 per thread -> 32 scalars
#define CAP  4096                 // SMEM candidate buffer (uint keys)

__device__ __forceinline__ unsigned fmap_u(unsigned b) {
    return b ^ ((unsigned)((int)b >> 31) | 0x80000000u);
}
__device__ __forceinline__ float funmap(unsigned u) {
    unsigned mask = ((unsigned)((int)(~u) >> 31)) | 0x80000000u;
    return __uint_as_float(u ^ mask);
}

__global__ __launch_bounds__(TPB, 4)
void wta_topk_kernel(const float4* __restrict__ x4,
                     const int*    __restrict__ kp,
                     float4*       __restrict__ o4)
{
    __shared__ unsigned sBuf[CAP];
    __shared__ unsigned sCnt;
    __shared__ unsigned sMax;
    __shared__ unsigned sRed[TPB / 32];
    __shared__ unsigned sTot;

    const int tid  = threadIdx.x;
    const int lane = tid & 31;
    const int warp = tid >> 5;
    const size_t base = (size_t)blockIdx.x * (COLS / 4) + tid;

    // ---- load row into registers as monotonic uint keys ----
    unsigned u[VPT * 4];
#pragma unroll
    for (int j = 0; j < VPT; j++) {
        float4 v = __ldcs(&x4[base + (size_t)j * TPB]);
        u[4 * j + 0] = fmap_u(__float_as_uint(v.x));
        u[4 * j + 1] = fmap_u(__float_as_uint(v.y));
        u[4 * j + 2] = fmap_u(__float_as_uint(v.z));
        u[4 * j + 3] = fmap_u(__float_as_uint(v.w));
    }

    const unsigned k = (unsigned)__ldg(kp);

    // ---- bisection: thr = max t with count(u >= t) >= k ----
    unsigned long long lo = 0ull, hi = 0x100000000ull;
    unsigned t = 0xBFC00000u;   // fmap(1.5f): E[count] ~547 for N(0,1) rows
    bool gathered = false;
    unsigned M = 0;

    while (hi - lo > 1ull) {
        unsigned cnt;
        if (!gathered) {
            // Full-row pass: count AND gather candidates into SMEM.
            if (tid == 0) { sCnt = 0u; sMax = 0u; }
            __syncthreads();
            unsigned lmax = 0u;
#pragma unroll
            for (int i = 0; i < VPT * 4; i++) {
                bool p = (u[i] >= t);
                unsigned m = __ballot_sync(0xffffffffu, p);
                if (p) {
                    int leader = __ffs(m) - 1;
                    unsigned rank = __popc(m & ((1u << lane) - 1u));
                    unsigned bpos = 0u;
                    if (lane == leader) bpos = atomicAdd(&sCnt, __popc(m));
                    bpos = __shfl_sync(m, bpos, leader);
                    unsigned pos = bpos + rank;
                    if (pos < CAP) sBuf[pos] = u[i];
                    lmax = max(lmax, u[i]);
                }
            }
#pragma unroll
            for (int o = 16; o; o >>= 1)
                lmax = max(lmax, __shfl_xor_sync(0xffffffffu, lmax, o));
            if (lane == 0) atomicMax(&sMax, lmax);
            __syncthreads();
            cnt = sCnt;
            if (cnt >= k) {
                lo = t;
                if (cnt <= CAP) {
                    gathered = true;
                    M = cnt;
                    unsigned long long h2 = (unsigned long long)sMax + 1ull;
                    if (h2 < hi) hi = h2;
                }
            } else {
                hi = t;
            }
            __syncthreads();
        } else {
            // Cheap pass: count over SMEM candidate set only.
            unsigned c = 0u;
            for (unsigned i = tid; i < M; i += TPB)
                c += (sBuf[i] >= t) ? 1u : 0u;
#pragma unroll
            for (int o = 16; o; o >>= 1)
                c += __shfl_xor_sync(0xffffffffu, c, o);
            if (lane == 0) sRed[warp] = c;
            __syncthreads();
            if (tid == 0) {
                unsigned s = 0u;
#pragma unroll
                for (int w = 0; w < TPB / 32; w++) s += sRed[w];
                sTot = s;
            }
            __syncthreads();
            cnt = sTot;
            if (cnt >= k) lo = t; else hi = t;
        }
        t = (unsigned)(lo + ((hi - lo) >> 1));
    }

    const unsigned thr = (unsigned)lo;

    // ---- exact counts at thr: cntGt = count(> thr), cntEq = count(== thr) ----
    {
        unsigned packed = 0u;   // (gt << 16) | eq ; both <= 8192 so no carry
#pragma unroll
        for (int i = 0; i < VPT * 4; i++) {
            packed += (u[i] > thr) ? 0x10000u : 0u;
            packed += (u[i] == thr) ? 1u : 0u;
        }
#pragma unroll
        for (int o = 16; o; o >>= 1)
            packed += __shfl_xor_sync(0xffffffffu, packed, o);
        __syncthreads();              // sRed reuse guard
        if (lane == 0) sRed[warp] = packed;
        __syncthreads();
        unsigned s = 0u;
#pragma unroll
        for (int w = 0; w < TPB / 32; w++) s += sRed[w];
        if (tid == 0) sTot = s;
        __syncthreads();
    }
    const unsigned cntGt = sTot >> 16;
    const unsigned cntEq = sTot & 0xFFFFu;

    // ---- tie resolution (rare): keep first (k - cntGt) of ==thr by column ----
    unsigned keepMask = 0xFFFFFFFFu;  // common case: keep all == thr
    if (cntGt + cntEq != k) {
        const unsigned t_keep = k - cntGt;   // cntGt < k by bisection invariant
        keepMask = 0u;
        unsigned running = 0u;               // eq elements in earlier j-slices
#pragma unroll 1
        for (int j = 0; j < VPT; j++) {
            unsigned e[4], lc = 0u;
#pragma unroll
            for (int c = 0; c < 4; c++) {
                e[c] = (u[4 * j + c] == thr) ? 1u : 0u;
                lc += e[c];
            }
            // warp inclusive scan of lc
            unsigned pre = lc;
#pragma unroll
            for (int o = 1; o < 32; o <<= 1) {
                unsigned n = __shfl_up_sync(0xffffffffu, pre, o);
                if (lane >= o) pre += n;
            }
            unsigned excl = pre - lc;
            __syncthreads();
            if (lane == 31) sRed[warp] = pre;
            __syncthreads();
            unsigned warpOff = 0u, total = 0u;
#pragma unroll
            for (int w = 0; w < TPB / 32; w++) {
                unsigned v = sRed[w];
                if (w < warp) warpOff += v;
                total += v;
            }
            unsigned r = running + warpOff + excl;
#pragma unroll
            for (int c = 0; c < 4; c++) {
                if (e[c]) {
                    if (r < t_keep) keepMask |= 1u << (4 * j + c);
                    r++;
                }
            }
            running += total;
        }
    }

    // ---- output pass: keep (> thr) or (== thr && kept-by-rank) ----
#pragma unroll
    for (int j = 0; j < VPT; j++) {
        float4 v;
#pragma unroll
        for (int c = 0; c < 4; c++) {
            const int i = 4 * j + c;
            bool keep = (u[i] > thr) ||
                        ((u[i] == thr) && ((keepMask >> i) & 1u));
            float f = keep ? funmap(u[i]) : 0.0f;
            if (c == 0) v.x = f;
            else if (c == 1) v.y = f;
            else if (c == 2) v.z = f;
            else v.w = f;
        }
        __stcs(&o4[base + (size_t)j * TPB], v);
    }
}

extern "C" void kernel_launch(void* const* d_in, const int* in_sizes, int n_in,
                              void* d_out, int out_size) {
    const float4* x4 = (const float4*)d_in[0];
    const int*    kp = (const int*)d_in[1];
    float4*       o4 = (float4*)d_out;
    const int rows = in_sizes[0] / COLS;
    wta_topk_kernel<<<rows, TPB>>>(x4, kp, o4);
}

// round 3
// speedup vs baseline: 1.9204x; 1.9204x over previous
#include <cuda_runtime.h>
#include <cuda_bf16.h>

// WTA / row-wise top-k(=64) scatter-to-dense, exact incl. stable tie-breaking.
// 1 CTA per row, row in registers (4x float4/thread, TPB=512).
//   (a) order-preserving float->uint key map
//   (b) gather candidates >= fmap(1.5) into SMEM via atomic cursor (~550 exp.)
//   (c) exact k-th key via 4-pass 256-bin radix select over candidates
//       (register-sourced radix fallback keeps arbitrary inputs correct)
//   (d) rare stable tie-break by column order, driven by radix metadata
//   (e) streaming output pass from registers.

#define COLS 8192
#define TPB  512
#define VPT  4                   // float4 per thread
#define NEL  (VPT * 4)           // 16 scalars per thread
#define CAP  2048                // SMEM candidate buffer
#define NW   (TPB / 32)

__device__ __forceinline__ unsigned fmap_u(unsigned b) {
    return b ^ ((unsigned)((int)b >> 31) | 0x80000000u);
}
__device__ __forceinline__ float funmap(unsigned v) {
    unsigned mask = ((unsigned)((int)(~v) >> 31)) | 0x80000000u;
    return __uint_as_float(v ^ mask);
}

__global__ __launch_bounds__(TPB, 3)
void wta_topk_kernel(const float4* __restrict__ x4,
                     const int*    __restrict__ kp,
                     float4*       __restrict__ o4)
{
    __shared__ unsigned sBuf[CAP];
    __shared__ unsigned sHist[256];
    __shared__ unsigned sWsum[NW];
    __shared__ unsigned sCnt, sSel, sNeed, sEq;

    const int tid  = threadIdx.x;
    const int lane = tid & 31;
    const int warp = tid >> 5;
    const size_t base = (size_t)blockIdx.x * (COLS / 4) + tid;

    // ---- load row into registers as monotonic uint keys ----
    unsigned u[NEL];
#pragma unroll
    for (int j = 0; j < VPT; j++) {
        float4 v = __ldcs(&x4[base + (size_t)j * TPB]);
        u[4 * j + 0] = fmap_u(__float_as_uint(v.x));
        u[4 * j + 1] = fmap_u(__float_as_uint(v.y));
        u[4 * j + 2] = fmap_u(__float_as_uint(v.z));
        u[4 * j + 3] = fmap_u(__float_as_uint(v.w));
    }
    const unsigned k = (unsigned)__ldg(kp);

    // ---- gather candidates >= T0 into SMEM (atomic cursor) ----
    if (tid == 0) sCnt = 0u;
    __syncthreads();
    const unsigned T0 = 0xBFC00000u;   // fmap(1.5f): E[count]~547 for N(0,1)
#pragma unroll
    for (int i = 0; i < NEL; i++) {
        if (u[i] >= T0) {
            unsigned p = atomicAdd(&sCnt, 1u);
            if (p < CAP) sBuf[p] = u[i];
        }
    }
    __syncthreads();
    const unsigned M = sCnt;
    const bool useBuf = (M >= k) && (M <= CAP);

    // ---- 4-pass 256-bin radix select for the k-th largest key ----
    unsigned prefix = 0u, need = k, eqCnt = 0u;
#pragma unroll
    for (int p = 3; p >= 0; p--) {
        const int sh = 8 * p;
        const unsigned hmask = (p == 3) ? 0u
                             : (0xFFFFFFFFu << ((sh + 8) & 31));
        if (tid < 256) sHist[tid] = 0u;
        __syncthreads();
        if (useBuf) {
            for (unsigned i = (unsigned)tid; i < M; i += TPB) {
                unsigned v = sBuf[i];
                if ((v & hmask) == prefix)
                    atomicAdd(&sHist[(v >> sh) & 255u], 1u);
            }
        } else {
#pragma unroll
            for (int i = 0; i < NEL; i++) {
                unsigned v = u[i];
                if ((v & hmask) == prefix)
                    atomicAdd(&sHist[(v >> sh) & 255u], 1u);
            }
        }
        __syncthreads();
        // reverse inclusive scan over 256 bins (bin idx = 255 - tid)
        unsigned v = 0u, incl = 0u;
        if (tid < 256) {
            v = sHist[255 - tid];
            incl = v;
#pragma unroll
            for (int o = 1; o < 32; o <<= 1) {
                unsigned n = __shfl_up_sync(0xffffffffu, incl, o);
                if (lane >= o) incl += n;
            }
            if (lane == 31) sWsum[warp] = incl;
        }
        __syncthreads();
        if (tid < 256) {
            unsigned add = 0u;
#pragma unroll
            for (int w = 0; w < 8; w++)
                if (w < warp) add += sWsum[w];
            incl += add;
            const unsigned excl = incl - v;
            if (excl < need && need <= incl) {   // exactly one bin fires
                sSel  = (unsigned)(255 - tid);
                sNeed = need - excl;
                sEq   = v;
            }
        }
        __syncthreads();
        prefix |= sSel << sh;
        need   = sNeed;
        eqCnt  = sEq;
    }

    const unsigned thr = prefix;   // exact k-th largest key
    // invariant: 1 <= need <= eqCnt ; count(> thr) = k - need

    // ---- rare stable tie-break: keep first `need` of ==thr by column ----
    unsigned keepMask = 0xFFFFFFFFu;   // common case (need == eqCnt): keep all
    if (need != eqCnt) {
        keepMask = 0u;
        unsigned running = 0u;
#pragma unroll 1
        for (int j = 0; j < VPT; j++) {
            unsigned e[4], lc = 0u;
#pragma unroll
            for (int c = 0; c < 4; c++) {
                e[c] = (u[4 * j + c] == thr) ? 1u : 0u;
                lc += e[c];
            }
            unsigned pre = lc;
#pragma unroll
            for (int o = 1; o < 32; o <<= 1) {
                unsigned n = __shfl_up_sync(0xffffffffu, pre, o);
                if (lane >= o) pre += n;
            }
            const unsigned excl = pre - lc;
            __syncthreads();
            if (lane == 31) sWsum[warp] = pre;
            __syncthreads();
            unsigned off = 0u, tot = 0u;
#pragma unroll
            for (int w = 0; w < NW; w++) {
                unsigned t = sWsum[w];
                if (w < warp) off += t;
                tot += t;
            }
            unsigned r = running + off + excl;
#pragma unroll
            for (int c = 0; c < 4; c++) {
                if (e[c]) {
                    if (r < need) keepMask |= 1u << (4 * j + c);
                    r++;
                }
            }
            running += tot;
        }
    }

    // ---- output pass: keep (> thr) or (== thr && kept-by-rank) ----
#pragma unroll
    for (int j = 0; j < VPT; j++) {
        float4 v;
#pragma unroll
        for (int c = 0; c < 4; c++) {
            const int i = 4 * j + c;
            const unsigned a = u[i];
            const bool keep = (a > thr) ||
                              ((a == thr) && ((keepMask >> i) & 1u));
            const float f = keep ? funmap(a) : 0.0f;
            if      (c == 0) v.x = f;
            else if (c == 1) v.y = f;
            else if (c == 2) v.z = f;
            else             v.w = f;
        }
        __stcs(&o4[base + (size_t)j * TPB], v);
    }
}

extern "C" void kernel_launch(void* const* d_in, const int* in_sizes, int n_in,
                              void* d_out, int out_size) {
    const float4* x4 = (const float4*)d_in[0];
    const int*    kp = (const int*)d_in[1];
    float4*       o4 = (float4*)d_out;
    const int rows = in_sizes[0] / COLS;
    wta_topk_kernel<<<rows, TPB>>>(x4, kp, o4);
}

// round 4
// speedup vs baseline: 2.0713x; 1.0786x over previous
#include <cuda_runtime.h>
#include <cuda_bf16.h>

// WTA / row-wise top-k(=64) scatter-to-dense, exact incl. stable tie-breaking.
// 1 CTA per row (TPB=512), row kept as raw floats in registers (4x float4).
//   (a) gather candidates f >= 1.5f into SMEM as order-preserving uint keys
//   (b) exact k-th key via 4-pass 256-bin radix select over candidates;
//       warp0 does bin selection (redux + 32-lane reverse scan)
//       (register-sourced radix fallback keeps arbitrary inputs correct)
//   (c) rare stable tie-break by column order
//   (d) streaming output: out = (f >= thrF) ? f : 0   (float-domain compare)

#define COLS 8192
#define TPB  512
#define VPT  4                   // float4 per thread
#define NEL  (VPT * 4)           // 16 scalars per thread
#define CAP  1024                // SMEM candidate buffer
#define NW   (TPB / 32)
#define FULL 0xffffffffu

__device__ __forceinline__ unsigned fmap_u(unsigned b) {
    return b ^ ((unsigned)((int)b >> 31) | 0x80000000u);
}
__device__ __forceinline__ float funmap(unsigned v) {
    unsigned mask = ((unsigned)((int)(~v) >> 31)) | 0x80000000u;
    return __uint_as_float(v ^ mask);
}

__global__ __launch_bounds__(TPB, 3)
void wta_topk_kernel(const float4* __restrict__ x4,
                     const int*    __restrict__ kp,
                     float4*       __restrict__ o4)
{
    __shared__ unsigned sBuf[CAP];
    __shared__ unsigned sHist[4 * 256];   // one 256-bin histogram per pass
    __shared__ unsigned sWsum[NW];
    __shared__ unsigned sCnt, sSel, sNeed, sEq;

    const int tid  = threadIdx.x;
    const int lane = tid & 31;
    const int warp = tid >> 5;
    const size_t base = (size_t)blockIdx.x * (COLS / 4) + tid;

    // ---- load row (raw floats) ----
    float4 v[VPT];
#pragma unroll
    for (int j = 0; j < VPT; j++)
        v[j] = __ldcs(&x4[base + (size_t)j * TPB]);
    const unsigned k = (unsigned)__ldg(kp);

    // ---- zero hists + cursor ----
    sHist[tid] = 0u;
    sHist[tid + 512] = 0u;
    if (tid == 0) sCnt = 0u;
    __syncthreads();

    // ---- gather candidates f >= T0F into SMEM as keys ----
    const float T0F = 1.5f;   // E[count] ~547 for N(0,1) rows
#pragma unroll
    for (int j = 0; j < VPT; j++) {
        const float e[4] = { v[j].x, v[j].y, v[j].z, v[j].w };
#pragma unroll
        for (int c = 0; c < 4; c++) {
            if (e[c] >= T0F) {
                unsigned p = atomicAdd(&sCnt, 1u);
                if (p < CAP) sBuf[p] = fmap_u(__float_as_uint(e[c]));
            }
        }
    }
    __syncthreads();
    const unsigned M = sCnt;
    const bool useBuf = (M >= k) && (M <= CAP);

    // ---- 4-pass 256-bin radix select for the k-th largest key ----
    unsigned prefix = 0u, need = k, eqCnt = 0u;
#pragma unroll
    for (int p = 3; p >= 0; p--) {
        const int sh = 8 * p;
        unsigned* H = &sHist[p * 256];
        // histogram of matching elements
        if (useBuf) {
            for (unsigned i = (unsigned)tid; i < M; i += TPB) {
                const unsigned key = sBuf[i];
                const bool m = (p == 3) || (((key ^ prefix) >> (sh + 8)) == 0u);
                if (m) atomicAdd(&H[(key >> sh) & 255u], 1u);
            }
        } else {
#pragma unroll
            for (int j = 0; j < VPT; j++) {
                const float e[4] = { v[j].x, v[j].y, v[j].z, v[j].w };
#pragma unroll
                for (int c = 0; c < 4; c++) {
                    const unsigned key = fmap_u(__float_as_uint(e[c]));
                    const bool m = (p == 3) || (((key ^ prefix) >> (sh + 8)) == 0u);
                    if (m) atomicAdd(&H[(key >> sh) & 255u], 1u);
                }
            }
        }
        __syncthreads();
        // warp0 selects the bin where reverse-cumulative crosses `need`
        if (warp == 0) {
            unsigned tot[8];
#pragma unroll
            for (int c = 0; c < 8; c++)
                tot[c] = __reduce_add_sync(FULL, H[c * 32 + lane]);
            unsigned suf = 0u, tch = 0u, exC = 0u;
#pragma unroll
            for (int c = 7; c >= 0; c--) {
                if (suf < need && need <= suf + tot[c]) { tch = (unsigned)c; exC = suf; }
                suf += tot[c];
            }
            const unsigned hv = H[tch * 32 + lane];
            unsigned incl = hv;
#pragma unroll
            for (int o = 1; o < 32; o <<= 1) {
                const unsigned n = __shfl_down_sync(FULL, incl, o);
                if (lane + o < 32) incl += n;
            }
            const unsigned excl = incl - hv;      // sum over higher bins in chunk
            if (exC + excl < need && need <= exC + incl) {
                sSel  = tch * 32 + (unsigned)lane;
                sNeed = need - exC - excl;
                sEq   = hv;
            }
        }
        __syncthreads();
        prefix |= sSel << sh;
        need   = sNeed;
        eqCnt  = sEq;
    }

    const float thrF = funmap(prefix);   // exact k-th largest value
    // invariant: 1 <= need <= eqCnt ; count(> thr) = k - need

    if (need == eqCnt) {
        // ---- common path: keep all f >= thrF ----
#pragma unroll
        for (int j = 0; j < VPT; j++) {
            float4 o;
            o.x = (v[j].x >= thrF) ? v[j].x : 0.0f;
            o.y = (v[j].y >= thrF) ? v[j].y : 0.0f;
            o.z = (v[j].z >= thrF) ? v[j].z : 0.0f;
            o.w = (v[j].w >= thrF) ? v[j].w : 0.0f;
            __stcs(&o4[base + (size_t)j * TPB], o);
        }
    } else {
        // ---- rare: stable tie-break, keep first `need` of ==thrF by column ----
        unsigned keepMask = 0u;
        unsigned running = 0u;
#pragma unroll 1
        for (int j = 0; j < VPT; j++) {
            const float e[4] = { v[j].x, v[j].y, v[j].z, v[j].w };
            unsigned eq[4], lc = 0u;
#pragma unroll
            for (int c = 0; c < 4; c++) {
                eq[c] = (e[c] == thrF) ? 1u : 0u;
                lc += eq[c];
            }
            unsigned pre = lc;
#pragma unroll
            for (int o = 1; o < 32; o <<= 1) {
                const unsigned n = __shfl_up_sync(FULL, pre, o);
                if (lane >= o) pre += n;
            }
            const unsigned excl = pre - lc;
            __syncthreads();
            if (lane == 31) sWsum[warp] = pre;
            __syncthreads();
            unsigned off = 0u, tot = 0u;
#pragma unroll
            for (int w = 0; w < NW; w++) {
                const unsigned t = sWsum[w];
                if (w < warp) off += t;
                tot += t;
            }
            unsigned r = running + off + excl;
#pragma unroll
            for (int c = 0; c < 4; c++) {
                if (eq[c]) {
                    if (r < need) keepMask |= 1u << (4 * j + c);
                    r++;
                }
            }
            running += tot;
        }
#pragma unroll
        for (int j = 0; j < VPT; j++) {
            const float e[4] = { v[j].x, v[j].y, v[j].z, v[j].w };
            float o[4];
#pragma unroll
            for (int c = 0; c < 4; c++) {
                const int i = 4 * j + c;
                const bool keep = (e[c] > thrF) ||
                                  ((e[c] == thrF) && ((keepMask >> i) & 1u));
                o[c] = keep ? e[c] : 0.0f;
            }
            float4 ov = { o[0], o[1], o[2], o[3] };
            __stcs(&o4[base + (size_t)j * TPB], ov);
        }
    }
}

extern "C" void kernel_launch(void* const* d_in, const int* in_sizes, int n_in,
                              void* d_out, int out_size) {
    const float4* x4 = (const float4*)d_in[0];
    const int*    kp = (const int*)d_in[1];
    float4*       o4 = (float4*)d_out;
    const int rows = in_sizes[0] / COLS;
    wta_topk_kernel<<<rows, TPB>>>(x4, kp, o4);
}

// round 5
// speedup vs baseline: 2.8200x; 1.3615x over previous
#include <cuda_runtime.h>
#include <cuda_bf16.h>

// WTA / row-wise top-k(=64) scatter-to-dense, exact incl. stable tie-breaking.
// 1 CTA per row (TPB=512), row as raw floats in registers (4x float4).
// Fast path (valid when count(f>=1.5) >= k, always true for N(0,1) rows):
//   (1) single 256-bin histogram of (bits>>16) over elements >= 1.5
//       -- positive-float bits are monotonic; [1.5,6) spans exactly 256 bins
//   (2) warp0 picks the bin where reverse-cumulative count crosses k
//   (3) gather that bin's elements (expected ~2, cap 32); warp0 computes the
//       exact k-th value + rank metadata with a 32-lane shuffle rank step
//   (4) streaming output: out = (f >= thr) ? f : 0 ; rare stable tie-break.
// Generic fallback (cold): 4-pass 256-bin radix select over fmap keys.

#define COLS 8192
#define TPB  512
#define VPT  4                    // float4 per thread -> 16 scalars
#define NW   (TPB / 32)
#define EMAX 32
#define FULL 0xffffffffu

__device__ __forceinline__ unsigned fmap_u(unsigned b) {
    return b ^ ((unsigned)((int)b >> 31) | 0x80000000u);
}
__device__ __forceinline__ float funmap(unsigned v) {
    unsigned mask = ((unsigned)((int)(~v) >> 31)) | 0x80000000u;
    return __uint_as_float(v ^ mask);
}

__global__ __launch_bounds__(TPB, 4)
void wta_topk_kernel(const float4* __restrict__ x4,
                     const int*    __restrict__ kp,
                     float4*       __restrict__ o4)
{
    __shared__ unsigned sHist[256];
    __shared__ unsigned sArr[EMAX];
    __shared__ unsigned sWsum[NW];
    __shared__ unsigned sCnt, sSel, sNeed, sEq, sThr, sFlag;

    const int tid  = threadIdx.x;
    const int lane = tid & 31;
    const int warp = tid >> 5;
    const size_t base = (size_t)blockIdx.x * (COLS / 4) + tid;

    // ---- load row (raw floats) ----
    float4 v[VPT];
#pragma unroll
    for (int j = 0; j < VPT; j++)
        v[j] = __ldcs(&x4[base + (size_t)j * TPB]);
    const unsigned k = (unsigned)__ldg(kp);

    if (tid < 256) sHist[tid] = 0u;
    if (tid == 0) { sCnt = 0u; sFlag = 0u; }
    __syncthreads();

    // ---- (1) one-pass histogram of (bits>>16)-0x3FC0 over f >= 1.5 ----
#pragma unroll
    for (int j = 0; j < VPT; j++) {
        const float e[4] = { v[j].x, v[j].y, v[j].z, v[j].w };
#pragma unroll
        for (int c = 0; c < 4; c++) {
            if (e[c] >= 1.5f) {
                unsigned b = (__float_as_uint(e[c]) >> 16) - 0x3FC0u;
                if (b > 255u) b = 255u;
                atomicAdd(&sHist[b], 1u);
            }
        }
    }
    __syncthreads();

    // ---- (2) warp0: pick bin where reverse-cumulative crosses k ----
    if (warp == 0) {
        unsigned hv8[8], tot[8];
#pragma unroll
        for (int c = 0; c < 8; c++) {
            hv8[c] = sHist[c * 32 + lane];
            tot[c] = __reduce_add_sync(FULL, hv8[c]);
        }
        unsigned suf = 0u, tch = 8u, exC = 0u;
#pragma unroll
        for (int c = 7; c >= 0; c--) {
            if (suf < k && k <= suf + tot[c]) { tch = (unsigned)c; exC = suf; }
            suf += tot[c];
        }
        if (suf < k) {                    // not enough candidates: fallback
            if (lane == 0) sFlag = 1u;
        } else {
            const unsigned hv = hv8[tch];
            unsigned incl = hv;           // sum over lanes >= lane (higher bins)
#pragma unroll
            for (int o = 1; o < 32; o <<= 1) {
                const unsigned n = __shfl_down_sync(FULL, incl, o);
                if (lane + o < 32) incl += n;
            }
            const unsigned excl = incl - hv;
            if (exC + excl < k && k <= exC + incl) {
                sSel  = tch * 32 + (unsigned)lane;
                sNeed = k - exC - excl;   // 1-based rank within bin
            }
        }
    }
    __syncthreads();

    float thrF;
    unsigned need, eqCnt;
    bool fastOK = (sFlag == 0u);

    if (fastOK) {
        // ---- (3a) gather selected-bin elements (full bits) ----
        const unsigned selBin = sSel;
#pragma unroll
        for (int j = 0; j < VPT; j++) {
            const float e[4] = { v[j].x, v[j].y, v[j].z, v[j].w };
#pragma unroll
            for (int c = 0; c < 4; c++) {
                if (e[c] >= 1.5f) {
                    const unsigned bits = __float_as_uint(e[c]);
                    unsigned b = (bits >> 16) - 0x3FC0u;
                    if (b > 255u) b = 255u;
                    if (b == selBin) {
                        const unsigned p = atomicAdd(&sCnt, 1u);
                        if (p < EMAX) sArr[p] = bits;
                    }
                }
            }
        }
        __syncthreads();
        const unsigned E = sCnt;
        if (E > EMAX) {
            fastOK = false;               // pathological bin: generic path
        } else {
            // ---- (3b) warp0: exact rank among E keys (E <= 32) ----
            if (warp == 0) {
                const unsigned need1 = sNeed;
                const unsigned key = (lane < (int)E) ? sArr[lane] : 0u;
                unsigned gt = 0u, eq = 0u;
#pragma unroll
                for (int o = 0; o < EMAX; o++) {
                    const unsigned other = __shfl_sync(FULL, key, o);
                    if (o < (int)E) {
                        gt += (other > key) ? 1u : 0u;
                        eq += (other == key) ? 1u : 0u;
                    }
                }
                if (gt < need1 && need1 <= gt + eq) {
                    sThr  = key;
                    sNeed = need1 - gt;
                    sEq   = eq;
                }
            }
            __syncthreads();
            thrF  = __uint_as_float(sThr);
            need  = sNeed;
            eqCnt = sEq;
        }
    }

    if (!fastOK) {
        // ---- generic fallback: 4-pass 256-bin radix over fmap keys ----
        unsigned prefix = 0u;
        need = k;
#pragma unroll 1
        for (int p = 3; p >= 0; p--) {
            const int sh = 8 * p;
            __syncthreads();
            if (tid < 256) sHist[tid] = 0u;
            __syncthreads();
#pragma unroll 1
            for (int j = 0; j < VPT; j++) {
                const float e[4] = { v[j].x, v[j].y, v[j].z, v[j].w };
#pragma unroll
                for (int c = 0; c < 4; c++) {
                    const unsigned key = fmap_u(__float_as_uint(e[c]));
                    const bool m = (p == 3) || (((key ^ prefix) >> (sh + 8)) == 0u);
                    if (m) atomicAdd(&sHist[(key >> sh) & 255u], 1u);
                }
            }
            __syncthreads();
            if (warp == 0) {
                unsigned hv8[8], tot[8];
#pragma unroll
                for (int c = 0; c < 8; c++) {
                    hv8[c] = sHist[c * 32 + lane];
                    tot[c] = __reduce_add_sync(FULL, hv8[c]);
                }
                unsigned suf = 0u, tch = 0u, exC = 0u;
#pragma unroll
                for (int c = 7; c >= 0; c--) {
                    if (suf < need && need <= suf + tot[c]) { tch = (unsigned)c; exC = suf; }
                    suf += tot[c];
                }
                const unsigned hv = hv8[tch];
                unsigned incl = hv;
#pragma unroll
                for (int o = 1; o < 32; o <<= 1) {
                    const unsigned n = __shfl_down_sync(FULL, incl, o);
                    if (lane + o < 32) incl += n;
                }
                const unsigned excl = incl - hv;
                if (exC + excl < need && need <= exC + incl) {
                    sSel  = tch * 32 + (unsigned)lane;
                    sNeed = need - exC - excl;
                    sEq   = hv;
                }
            }
            __syncthreads();
            prefix |= sSel << sh;
            need   = sNeed;
        }
        eqCnt = sEq;
        thrF  = funmap(prefix);
    }

    // ---- (4) output ----
    if (need == eqCnt) {
        // common path: keep all f >= thrF
#pragma unroll
        for (int j = 0; j < VPT; j++) {
            float4 o;
            o.x = (v[j].x >= thrF) ? v[j].x : 0.0f;
            o.y = (v[j].y >= thrF) ? v[j].y : 0.0f;
            o.z = (v[j].z >= thrF) ? v[j].z : 0.0f;
            o.w = (v[j].w >= thrF) ? v[j].w : 0.0f;
            __stcs(&o4[base + (size_t)j * TPB], o);
        }
    } else {
        // rare: stable tie-break, keep first `need` of ==thrF by column order
        unsigned keepMask = 0u;
        unsigned running = 0u;
#pragma unroll 1
        for (int j = 0; j < VPT; j++) {
            const float e[4] = { v[j].x, v[j].y, v[j].z, v[j].w };
            unsigned eq[4], lc = 0u;
#pragma unroll
            for (int c = 0; c < 4; c++) {
                eq[c] = (e[c] == thrF) ? 1u : 0u;
                lc += eq[c];
            }
            unsigned pre = lc;
#pragma unroll
            for (int o = 1; o < 32; o <<= 1) {
                const unsigned n = __shfl_up_sync(FULL, pre, o);
                if (lane >= o) pre += n;
            }
            const unsigned excl = pre - lc;
            __syncthreads();
            if (lane == 31) sWsum[warp] = pre;
            __syncthreads();
            unsigned off = 0u, tot = 0u;
#pragma unroll
            for (int w = 0; w < NW; w++) {
                const unsigned t = sWsum[w];
                if (w < warp) off += t;
                tot += t;
            }
            unsigned r = running + off + excl;
#pragma unroll
            for (int c = 0; c < 4; c++) {
                if (eq[c]) {
                    if (r < need) keepMask |= 1u << (4 * j + c);
                    r++;
                }
            }
            running += tot;
        }
#pragma unroll
        for (int j = 0; j < VPT; j++) {
            const float e[4] = { v[j].x, v[j].y, v[j].z, v[j].w };
            float o[4];
#pragma unroll
            for (int c = 0; c < 4; c++) {
                const int i = 4 * j + c;
                const bool keep = (e[c] > thrF) ||
                                  ((e[c] == thrF) && ((keepMask >> i) & 1u));
                o[c] = keep ? e[c] : 0.0f;
            }
            float4 ov = { o[0], o[1], o[2], o[3] };
            __stcs(&o4[base + (size_t)j * TPB], ov);
        }
    }
}

extern "C" void kernel_launch(void* const* d_in, const int* in_sizes, int n_in,
                              void* d_out, int out_size) {
    const float4* x4 = (const float4*)d_in[0];
    const int*    kp = (const int*)d_in[1];
    float4*       o4 = (float4*)d_out;
    const int rows = in_sizes[0] / COLS;
    wta_topk_kernel<<<rows, TPB>>>(x4, kp, o4);
}

// round 6
// speedup vs baseline: 2.9979x; 1.0631x over previous
#include <cuda_runtime.h>
#include <cuda_bf16.h>

// WTA / row-wise top-k(=64) scatter-to-dense, exact incl. stable tie-breaking.
// 1 CTA per row (TPB=512), row as raw floats in registers (4x float4).
// Fast path (valid when count(f>=1.5) >= k, always true for N(0,1) rows):
//   (1) single fused pass: histogram of (bits>>16)-0x3FC0 over f >= 1.5
//       AND capture each candidate's bits into its bin's slot array
//       (slot index = atomicAdd return). [1.5,6) spans exactly 256 bins.
//   (2) warp0, one region: pick bin where reverse-cumulative crosses k,
//       then shuffle-rank the <=16 captured elements -> exact k-th value.
//   (3) streaming output: out = (f >= thr) ? f : 0 ; rare stable tie-break.
// Generic fallback (cold, exact): 4-pass 256-bin radix select over fmap keys.

#define COLS  8192
#define TPB   512
#define VPT   4                    // float4 per thread -> 16 scalars
#define NW    (TPB / 32)
#define SLOTS 16
#define FULL  0xffffffffu

__device__ __forceinline__ unsigned fmap_u(unsigned b) {
    return b ^ ((unsigned)((int)b >> 31) | 0x80000000u);
}
__device__ __forceinline__ float funmap(unsigned v) {
    unsigned mask = ((unsigned)((int)(~v) >> 31)) | 0x80000000u;
    return __uint_as_float(v ^ mask);
}

__global__ __launch_bounds__(TPB, 4)
void wta_topk_kernel(const float4* __restrict__ x4,
                     const int*    __restrict__ kp,
                     float4*       __restrict__ o4)
{
    __shared__ unsigned sHist[256];
    __shared__ unsigned sBinData[256 * SLOTS];
    __shared__ unsigned sWsum[NW];
    __shared__ unsigned sSel, sNeed, sEq, sThr, sFlag;

    const int tid  = threadIdx.x;
    const int lane = tid & 31;
    const int warp = tid >> 5;
    const size_t base = (size_t)blockIdx.x * (COLS / 4) + tid;

    // ---- load row (raw floats) ----
    float4 v[VPT];
#pragma unroll
    for (int j = 0; j < VPT; j++)
        v[j] = __ldcs(&x4[base + (size_t)j * TPB]);
    const unsigned k = (unsigned)__ldg(kp);

    if (tid < 256) sHist[tid] = 0u;
    if (tid == 0) sFlag = 0u;
    __syncthreads();

    // ---- (1) fused histogram + candidate capture over f >= 1.5 ----
#pragma unroll
    for (int j = 0; j < VPT; j++) {
#pragma unroll
        for (int c = 0; c < 4; c++) {
            const float f = (c == 0) ? v[j].x : (c == 1) ? v[j].y
                          : (c == 2) ? v[j].z : v[j].w;
            if (f >= 1.5f) {
                const unsigned bits = __float_as_uint(f);
                unsigned b = (bits >> 16) - 0x3FC0u;
                b = min(b, 255u);
                const unsigned p = atomicAdd(&sHist[b], 1u);
                if (p < SLOTS) sBinData[(b << 4) + p] = bits;
            }
        }
    }
    __syncthreads();

    // ---- (2) warp0: bin select + in-bin shuffle rank (one region) ----
    if (warp == 0) {
        unsigned hv8[8], tot[8];
#pragma unroll
        for (int c = 0; c < 8; c++) {
            hv8[c] = sHist[c * 32 + lane];
            tot[c] = __reduce_add_sync(FULL, hv8[c]);
        }
        unsigned suf = 0u, tch = 0u, exC = 0u;
#pragma unroll
        for (int c = 7; c >= 0; c--) {
            if (suf < k && k <= suf + tot[c]) { tch = (unsigned)c; exC = suf; }
            suf += tot[c];
        }
        if (suf < k) {
            if (lane == 0) sFlag = 1u;
        } else {
            const unsigned hv = hv8[tch];
            unsigned incl = hv;           // suffix sum: bins >= this lane's bin
#pragma unroll
            for (int o = 1; o < 32; o <<= 1) {
                const unsigned n = __shfl_down_sync(FULL, incl, o);
                if (lane + o < 32) incl += n;
            }
            const unsigned excl = incl - hv;
            const bool fired = (exC + excl < k) && (k <= exC + incl);
            const unsigned fm = __ballot_sync(FULL, fired);
            const int src = __ffs(fm) - 1;
            const unsigned selBin = tch * 32u + (unsigned)src;
            const unsigned need1  = k - exC - __shfl_sync(FULL, excl, src);
            const unsigned E      = __shfl_sync(FULL, hv, src);
            if (E > SLOTS) {
                if (lane == 0) sFlag = 1u;
            } else {
                // rank among E (<=16) captured keys: positive-float bits
                // compare identically to values.
                const unsigned key = (lane < (int)E)
                                   ? sBinData[(selBin << 4) + lane] : 0u;
                unsigned gt = 0u, eq = 0u;
#pragma unroll
                for (int o = 0; o < SLOTS; o++) {
                    const unsigned other = __shfl_sync(FULL, key, o);
                    if (o < (int)E) {
                        gt += (other > key) ? 1u : 0u;
                        eq += (other == key) ? 1u : 0u;
                    }
                }
                if (gt < need1 && need1 <= gt + eq) {   // unique key fires
                    sThr  = key;
                    sNeed = need1 - gt;
                    sEq   = eq;
                }
            }
        }
    }
    __syncthreads();

    float thrF;
    unsigned need, eqCnt;

    if (sFlag == 0u) {
        thrF  = __uint_as_float(sThr);
        need  = sNeed;
        eqCnt = sEq;
    } else {
        // ---- generic fallback: 4-pass 256-bin radix over fmap keys ----
        unsigned prefix = 0u;
        need = k;
#pragma unroll 1
        for (int p = 3; p >= 0; p--) {
            const int sh = 8 * p;
            __syncthreads();
            if (tid < 256) sHist[tid] = 0u;
            __syncthreads();
#pragma unroll 1
            for (int j = 0; j < VPT; j++) {
                const float e[4] = { v[j].x, v[j].y, v[j].z, v[j].w };
#pragma unroll
                for (int c = 0; c < 4; c++) {
                    const unsigned key = fmap_u(__float_as_uint(e[c]));
                    const bool m = (p == 3) || (((key ^ prefix) >> (sh + 8)) == 0u);
                    if (m) atomicAdd(&sHist[(key >> sh) & 255u], 1u);
                }
            }
            __syncthreads();
            if (warp == 0) {
                unsigned hv8[8], tot[8];
#pragma unroll
                for (int c = 0; c < 8; c++) {
                    hv8[c] = sHist[c * 32 + lane];
                    tot[c] = __reduce_add_sync(FULL, hv8[c]);
                }
                unsigned suf = 0u, tch = 0u, exC = 0u;
#pragma unroll
                for (int c = 7; c >= 0; c--) {
                    if (suf < need && need <= suf + tot[c]) { tch = (unsigned)c; exC = suf; }
                    suf += tot[c];
                }
                const unsigned hv = hv8[tch];
                unsigned incl = hv;
#pragma unroll
                for (int o = 1; o < 32; o <<= 1) {
                    const unsigned n = __shfl_down_sync(FULL, incl, o);
                    if (lane + o < 32) incl += n;
                }
                const unsigned excl = incl - hv;
                if (exC + excl < need && need <= exC + incl) {
                    sSel  = tch * 32 + (unsigned)lane;
                    sNeed = need - exC - excl;
                    sEq   = hv;
                }
            }
            __syncthreads();
            prefix |= sSel << sh;
            need   = sNeed;
        }
        eqCnt = sEq;
        thrF  = funmap(prefix);
    }

    // ---- (3) output ----
    if (need == eqCnt) {
        // common path: keep all f >= thrF
#pragma unroll
        for (int j = 0; j < VPT; j++) {
            float4 o;
            o.x = (v[j].x >= thrF) ? v[j].x : 0.0f;
            o.y = (v[j].y >= thrF) ? v[j].y : 0.0f;
            o.z = (v[j].z >= thrF) ? v[j].z : 0.0f;
            o.w = (v[j].w >= thrF) ? v[j].w : 0.0f;
            __stcs(&o4[base + (size_t)j * TPB], o);
        }
    } else {
        // rare: stable tie-break, keep first `need` of ==thrF by column order
        unsigned keepMask = 0u;
        unsigned running = 0u;
#pragma unroll 1
        for (int j = 0; j < VPT; j++) {
            const float e[4] = { v[j].x, v[j].y, v[j].z, v[j].w };
            unsigned eq[4], lc = 0u;
#pragma unroll
            for (int c = 0; c < 4; c++) {
                eq[c] = (e[c] == thrF) ? 1u : 0u;
                lc += eq[c];
            }
            unsigned pre = lc;
#pragma unroll
            for (int o = 1; o < 32; o <<= 1) {
                const unsigned n = __shfl_up_sync(FULL, pre, o);
                if (lane >= o) pre += n;
            }
            const unsigned excl = pre - lc;
            __syncthreads();
            if (lane == 31) sWsum[warp] = pre;
            __syncthreads();
            unsigned off = 0u, tot = 0u;
#pragma unroll
            for (int w = 0; w < NW; w++) {
                const unsigned t = sWsum[w];
                if (w < warp) off += t;
                tot += t;
            }
            unsigned r = running + off + excl;
#pragma unroll
            for (int c = 0; c < 4; c++) {
                if (eq[c]) {
                    if (r < need) keepMask |= 1u << (4 * j + c);
                    r++;
                }
            }
            running += tot;
        }
#pragma unroll
        for (int j = 0; j < VPT; j++) {
            const float e[4] = { v[j].x, v[j].y, v[j].z, v[j].w };
            float o[4];
#pragma unroll
            for (int c = 0; c < 4; c++) {
                const int i = 4 * j + c;
                const bool keep = (e[c] > thrF) ||
                                  ((e[c] == thrF) && ((keepMask >> i) & 1u));
                o[c] = keep ? e[c] : 0.0f;
            }
            float4 ov = { o[0], o[1], o[2], o[3] };
            __stcs(&o4[base + (size_t)j * TPB], ov);
        }
    }
}

extern "C" void kernel_launch(void* const* d_in, const int* in_sizes, int n_in,
                              void* d_out, int out_size) {
    const float4* x4 = (const float4*)d_in[0];
    const int*    kp = (const int*)d_in[1];
    float4*       o4 = (float4*)d_out;
    const int rows = in_sizes[0] / COLS;
    wta_topk_kernel<<<rows, TPB>>>(x4, kp, o4);
}